// round 2
// baseline (speedup 1.0000x reference)
#include <cuda_runtime.h>
#include <cuda_bf16.h>
#include <math.h>

// Problem constants
#define BATCH 32
#define TT 64
#define SS 64
#define VV 32000
#define EE 512
#define HH 512

// ---------------- device scratch (no cudaMalloc allowed) ----------------
__device__ float g_embT[TT * BATCH * EE];        // [t][b][e]
__device__ float g_h[2 * BATCH * HH];            // [l][b][h]
__device__ float g_c[2 * BATCH * HH];
__device__ float g_feat[TT * BATCH * 1024];      // [t][b][ h1(512) | ctx(512) ]
__device__ float g_gpart[12 * BATCH * 2048];     // gate partial sums (k-sliced)
__device__ float g_qpart[4 * BATCH * HH];        // q partial sums

// ---------------- utility kernels ----------------
__global__ void init_state_kernel(const float* __restrict__ hidden,
                                  const float* __restrict__ cell) {
    int i = blockIdx.x * blockDim.x + threadIdx.x;
    if (i < 2 * BATCH * HH) { g_h[i] = hidden[i]; g_c[i] = cell[i]; }
}

__global__ void tail_copy_kernel(float* __restrict__ out) {
    int i = blockIdx.x * blockDim.x + threadIdx.x;
    const long long OFF = (long long)BATCH * TT * VV;
    if (i < 2 * BATCH * HH) {
        out[OFF + i] = g_h[i];
        out[OFF + 2 * BATCH * HH + i] = g_c[i];
    }
}

// embedded[t][b][:] = (tgt[b][t]==0) ? 0 : emb[tgt[b][t]]
__global__ void embed_kernel(const int* __restrict__ tgt,
                             const float* __restrict__ emb) {
    int blk = blockIdx.x;             // b*TT + t
    int b = blk >> 6, t = blk & 63;
    int idx = tgt[blk];
    const float4* src = reinterpret_cast<const float4*>(emb + (long long)idx * EE);
    float4* dst = reinterpret_cast<float4*>(g_embT + ((long long)t * BATCH + b) * EE);
    float4 v;
    if (idx == 0) { v.x = v.y = v.z = v.w = 0.f; }
    else          { v = src[threadIdx.x]; }
    dst[threadIdx.x] = v;
}

// ---------------- small-M (M=32) partial GEMM: C = A @ W^T ----------------
// Each op: A [32 x 512] (row stride sA), W [N x 512] (row stride sW).
// Grid: (N/64, nops*4).  blockIdx.y -> op = y>>2, k-slice = y&3 (128 k each).
// Writes partial C into Cpart + blockIdx.y * 32*ldc.
__global__ __launch_bounds__(256)
void gates_kernel(const float* __restrict__ A0, int sA0, const float* __restrict__ W0, int sW0,
                  const float* __restrict__ A1, int sA1, const float* __restrict__ W1, int sW1,
                  const float* __restrict__ A2, int sA2, const float* __restrict__ W2, int sW2,
                  float* __restrict__ Cpart, int ldc) {
    __shared__ float As[32][33];
    __shared__ float Ws[32][68];
    const int tid = threadIdx.x;
    const int jg = tid & 15;
    const int bg = tid >> 4;
    const int j0 = blockIdx.x * 64;
    const int jj0 = jg * 4;
    const int b0 = bg * 2;

    const int op = blockIdx.y >> 2;
    const int ksl = blockIdx.y & 3;

    const float* A = (op == 0) ? A0 : (op == 1) ? A1 : A2;
    const float* W = (op == 0) ? W0 : (op == 1) ? W1 : W2;
    const int sA = (op == 0) ? sA0 : (op == 1) ? sA1 : sA2;
    const int sW = (op == 0) ? sW0 : (op == 1) ? sW1 : sW2;

    float acc[2][4];
    #pragma unroll
    for (int i = 0; i < 2; i++)
        #pragma unroll
        for (int j = 0; j < 4; j++) acc[i][j] = 0.f;

    const int kbase = ksl * 128;
    for (int k0 = kbase; k0 < kbase + 128; k0 += 32) {
        #pragma unroll
        for (int i = 0; i < 4; i++) {
            int e = tid + i * 256;
            int bb = e >> 5, kk = e & 31;
            As[kk][bb] = A[bb * sA + k0 + kk];
        }
        #pragma unroll
        for (int i = 0; i < 8; i++) {
            int e = tid + i * 256;
            int jj = e >> 5, kk = e & 31;
            Ws[kk][jj] = W[(long long)(j0 + jj) * sW + k0 + kk];
        }
        __syncthreads();
        #pragma unroll
        for (int kk = 0; kk < 32; kk++) {
            float a0 = As[kk][b0];
            float a1 = As[kk][b0 + 1];
            float4 wv = *reinterpret_cast<const float4*>(&Ws[kk][jj0]);
            acc[0][0] += a0 * wv.x; acc[0][1] += a0 * wv.y;
            acc[0][2] += a0 * wv.z; acc[0][3] += a0 * wv.w;
            acc[1][0] += a1 * wv.x; acc[1][1] += a1 * wv.y;
            acc[1][2] += a1 * wv.z; acc[1][3] += a1 * wv.w;
        }
        __syncthreads();
    }

    float* C = Cpart + (long long)blockIdx.y * 32 * ldc;
    #pragma unroll
    for (int i = 0; i < 2; i++) {
        int b = b0 + i;
        #pragma unroll
        for (int j = 0; j < 4; j++)
            C[b * ldc + j0 + jj0 + j] = acc[i][j];
    }
}

// ---------------- LSTM elementwise update (sums k-slice partials) ----------------
__device__ __forceinline__ float sigmf(float x) { return 1.f / (1.f + expf(-x)); }

__global__ void lstm_update_kernel(const float* __restrict__ gpart, int nslices,
                                   const float* __restrict__ b_ih,
                                   const float* __restrict__ b_hh,
                                   float* __restrict__ h, float* __restrict__ c,
                                   float* __restrict__ feat_h1) {
    int idx = blockIdx.x * blockDim.x + threadIdx.x;
    if (idx >= BATCH * HH) return;
    int b = idx >> 9, u = idx & 511;
    float gi = 0, gf = 0, gg = 0, go = 0;
    for (int s = 0; s < nslices; s++) {
        const float* gp = gpart + (long long)s * BATCH * 2048 + b * 2048;
        gi += gp[u]; gf += gp[512 + u]; gg += gp[1024 + u]; go += gp[1536 + u];
    }
    gi += b_ih[u]        + b_hh[u];
    gf += b_ih[512 + u]  + b_hh[512 + u];
    gg += b_ih[1024 + u] + b_hh[1024 + u];
    go += b_ih[1536 + u] + b_hh[1536 + u];
    float cn = sigmf(gf) * c[idx] + sigmf(gi) * tanhf(gg);
    float hn = sigmf(go) * tanhf(cn);
    c[idx] = cn;
    h[idx] = hn;
    if (feat_h1) feat_h1[b * 1024 + u] = hn;
}

// ---------------- attention: scores, softmax, context ----------------
// grid = 32 (one block per batch), block = 256
__global__ void attn_kernel(const float* __restrict__ enc,   // [B,S,H]
                            float* __restrict__ ctx_out) {    // g_feat + t*32*1024 + 512
    __shared__ float q_sm[HH];
    __shared__ float sc[SS];
    __shared__ float s_red[2];
    const int b = blockIdx.x;
    const int tid = threadIdx.x;
    const int lane = tid & 31;
    const int warp = tid >> 5;

    // q[b][k] = sum of 4 k-slice partials
    #pragma unroll
    for (int r = 0; r < 2; r++) {
        int k = tid + r * 256;
        float v = 0.f;
        #pragma unroll
        for (int s = 0; s < 4; s++) v += g_qpart[s * BATCH * HH + b * HH + k];
        q_sm[k] = v;
    }
    __syncthreads();

    // scores[s] = enc[b,s,:] . q   (8 warps x 8 scores)
    const float* encb = enc + (long long)b * SS * HH;
    #pragma unroll
    for (int si = 0; si < 8; si++) {
        int s = warp * 8 + si;
        const float* row = encb + s * HH;
        float sum = 0.f;
        for (int j = lane; j < HH; j += 32) sum += row[j] * q_sm[j];
        #pragma unroll
        for (int o = 16; o; o >>= 1) sum += __shfl_down_sync(0xffffffffu, sum, o);
        if (lane == 0) sc[s] = sum;
    }
    __syncthreads();

    if (tid == 0) {
        float mx = sc[0];
        for (int s = 1; s < SS; s++) mx = fmaxf(mx, sc[s]);
        s_red[0] = mx;
    }
    __syncthreads();
    if (tid < SS) sc[tid] = expf(sc[tid] - s_red[0]);
    __syncthreads();
    if (tid == 0) {
        float sm = 0.f;
        for (int s = 0; s < SS; s++) sm += sc[s];
        s_red[1] = 1.f / sm;
    }
    __syncthreads();
    const float inv = s_red[1];

    // context[k] = sum_s attn[s] * enc[b,s,k]
    for (int k = tid; k < HH; k += 256) {
        float acc = 0.f;
        #pragma unroll 8
        for (int s = 0; s < SS; s++) acc += sc[s] * encb[s * HH + k];
        ctx_out[b * 1024 + k] = acc * inv;
    }
}

// ---------------- final projection GEMM ----------------
// out[(b*64+t)*V + n] = feat[t*32+b,:] . W_out[n,:] + b_out[n]
// A = g_feat [2048 x 1024], W [32000 x 1024]. 128x128x16 tiles, 8x8 micro.
__global__ __launch_bounds__(256, 2)
void big_gemm_kernel(const float* __restrict__ A,
                     const float* __restrict__ W,
                     const float* __restrict__ bias,
                     float* __restrict__ out) {
    __shared__ float As[16][132];
    __shared__ float Ws[16][132];
    const int tid = threadIdx.x;
    const int m0 = blockIdx.y * 128;
    const int n0 = blockIdx.x * 128;
    const int tm = (tid >> 4) * 8;
    const int tn = (tid & 15) * 8;
    const int ar = tid >> 2;
    const int ac = (tid & 3) * 4;
    const int K = 1024;

    float acc[8][8];
    #pragma unroll
    for (int i = 0; i < 8; i++)
        #pragma unroll
        for (int j = 0; j < 8; j++) acc[i][j] = 0.f;

    for (int k0 = 0; k0 < K; k0 += 16) {
        #pragma unroll
        for (int i = 0; i < 2; i++) {
            int r = ar + i * 64;
            float4 v = *reinterpret_cast<const float4*>(&A[(long long)(m0 + r) * K + k0 + ac]);
            As[ac + 0][r] = v.x; As[ac + 1][r] = v.y; As[ac + 2][r] = v.z; As[ac + 3][r] = v.w;
            float4 u = *reinterpret_cast<const float4*>(&W[(long long)(n0 + r) * K + k0 + ac]);
            Ws[ac + 0][r] = u.x; Ws[ac + 1][r] = u.y; Ws[ac + 2][r] = u.z; Ws[ac + 3][r] = u.w;
        }
        __syncthreads();
        #pragma unroll
        for (int kk = 0; kk < 16; kk++) {
            float a[8], w[8];
            *reinterpret_cast<float4*>(&a[0]) = *reinterpret_cast<const float4*>(&As[kk][tm]);
            *reinterpret_cast<float4*>(&a[4]) = *reinterpret_cast<const float4*>(&As[kk][tm + 4]);
            *reinterpret_cast<float4*>(&w[0]) = *reinterpret_cast<const float4*>(&Ws[kk][tn]);
            *reinterpret_cast<float4*>(&w[4]) = *reinterpret_cast<const float4*>(&Ws[kk][tn + 4]);
            #pragma unroll
            for (int i = 0; i < 8; i++)
                #pragma unroll
                for (int j = 0; j < 8; j++)
                    acc[i][j] += a[i] * w[j];
        }
        __syncthreads();
    }

    #pragma unroll
    for (int i = 0; i < 8; i++) {
        int m = m0 + tm + i;
        int t = m >> 5, b = m & 31;
        float* orow = out + ((long long)(b * 64 + t)) * VV + n0 + tn;
        #pragma unroll
        for (int j = 0; j < 8; j++)
            orow[j] = acc[i][j] + bias[n0 + tn + j];
    }
}

// ---------------- host launcher ----------------
extern "C" void kernel_launch(void* const* d_in, const int* in_sizes, int n_in,
                              void* d_out, int out_size) {
    const int*   tgt    = (const int*)  d_in[0];
    const float* enc    = (const float*)d_in[1];
    const float* hidden = (const float*)d_in[2];
    const float* cell   = (const float*)d_in[3];
    const float* emb    = (const float*)d_in[4];
    const float* W_a    = (const float*)d_in[5];
    const float* W_ih0  = (const float*)d_in[6];
    const float* W_hh0  = (const float*)d_in[7];
    const float* b_ih0  = (const float*)d_in[8];
    const float* b_hh0  = (const float*)d_in[9];
    const float* W_ih1  = (const float*)d_in[10];
    const float* W_hh1  = (const float*)d_in[11];
    const float* b_ih1  = (const float*)d_in[12];
    const float* b_hh1  = (const float*)d_in[13];
    const float* W_out  = (const float*)d_in[14];
    const float* b_out  = (const float*)d_in[15];
    float* out = (float*)d_out;

    float *p_embT, *p_h, *p_c, *p_feat, *p_gpart, *p_qpart;
    cudaGetSymbolAddress((void**)&p_embT,  g_embT);
    cudaGetSymbolAddress((void**)&p_h,     g_h);
    cudaGetSymbolAddress((void**)&p_c,     g_c);
    cudaGetSymbolAddress((void**)&p_feat,  g_feat);
    cudaGetSymbolAddress((void**)&p_gpart, g_gpart);
    cudaGetSymbolAddress((void**)&p_qpart, g_qpart);

    init_state_kernel<<<64, 512>>>(hidden, cell);
    embed_kernel<<<BATCH * TT, 128>>>(tgt, emb);

    for (int t = 0; t < TT; t++) {
        float* embT_t = p_embT + (long long)t * BATCH * EE;
        float* feat_t = p_feat + (long long)t * BATCH * 1024;
        float* ctx_t  = feat_t + 512;   // [b][512..1023], row stride 1024

        // q = W_a @ h1 per batch row: q[b,j] = sum_k W_a[j,k] * h1[b,k]
        gates_kernel<<<dim3(8, 4), 256>>>(
            p_h + BATCH * HH, 512, W_a, 512,
            p_h, 512, W_a, 512,
            p_h, 512, W_a, 512,
            p_qpart, 512);

        // attention -> context into feat[t][b][512:]
        attn_kernel<<<32, 256>>>(enc, ctx_t);

        // LSTM0 gates: emb@Wih0[:, :512]^T + ctx@Wih0[:, 512:]^T + h0@Whh0^T
        gates_kernel<<<dim3(32, 12), 256>>>(
            embT_t, 512, W_ih0, 1024,
            ctx_t, 1024, W_ih0 + 512, 1024,
            p_h, 512, W_hh0, 512,
            p_gpart, 2048);
        lstm_update_kernel<<<64, 256>>>(p_gpart, 12, b_ih0, b_hh0,
                                        p_h, p_c, nullptr);

        // LSTM1 gates: h0@Wih1^T + h1@Whh1^T
        gates_kernel<<<dim3(32, 8), 256>>>(
            p_h, 512, W_ih1, 512,
            p_h + BATCH * HH, 512, W_hh1, 512,
            p_h, 512, W_ih1, 512,
            p_gpart, 2048);
        lstm_update_kernel<<<64, 256>>>(p_gpart, 8, b_ih1, b_hh1,
                                        p_h + BATCH * HH, p_c + BATCH * HH,
                                        feat_t);
    }

    // final projection: [2048,1024] @ [32000,1024]^T with (t,b)->(b,t) remap
    big_gemm_kernel<<<dim3(VV / 128, 16), 256>>>(p_feat, W_out, b_out, out);

    tail_copy_kernel<<<64, 512>>>(out);
}

// round 4
// speedup vs baseline: 1.4090x; 1.4090x over previous
#include <cuda_runtime.h>
#include <cuda_bf16.h>
#include <math.h>
#include <stdint.h>

// Problem constants
#define BATCH 32
#define TT 64
#define SS 64
#define VV 32000
#define EE 512
#define HH 512

// ---------------- device scratch (no cudaMalloc allowed) ----------------
__device__ float g_embT[TT * BATCH * EE];        // [t][b][e]
__device__ float g_h[2 * BATCH * HH];            // [l][b][h]
__device__ float g_c[2 * BATCH * HH];
__device__ float g_feat[TT * BATCH * 1024];      // [t][b][ h1(512) | ctx(512) ]
__device__ float g_gpart[12 * BATCH * 2048];     // gate partial sums (k-sliced)
__device__ float g_qpart[4 * BATCH * HH];        // q partial sums
// bf16 split operands for tensor-core projection GEMM
__device__ __nv_bfloat16 g_WH[VV * 1024];        // W_out hi (64MB)
__device__ __nv_bfloat16 g_WL[VV * 1024];        // W_out lo (64MB)
__device__ __nv_bfloat16 g_fH[2048 * 1024];      // feat hi
__device__ __nv_bfloat16 g_fL[2048 * 1024];      // feat lo

// ---------------- PTX helpers (sm_80-tier: compile for plain compute_103) ----
__device__ __forceinline__ uint32_t smem_to_u32(const void* p) {
    uint32_t a;
    asm("{ .reg .u64 t; cvta.to.shared.u64 t, %1; cvt.u32.u64 %0, t; }" : "=r"(a) : "l"(p));
    return a;
}
#define CP16(dst, src) \
    asm volatile("cp.async.cg.shared.global [%0], [%1], 16;" \
                 :: "r"(dst), "l"(src) : "memory")
#define CP_COMMIT() asm volatile("cp.async.commit_group;" ::: "memory")
#define CP_WAIT0()  asm volatile("cp.async.wait_group 0;" ::: "memory")
#define CP_WAIT1()  asm volatile("cp.async.wait_group 1;" ::: "memory")

#define LDSM_X4(r0, r1, r2, r3, addr) \
    asm volatile("ldmatrix.sync.aligned.m8n8.x4.shared.b16 {%0,%1,%2,%3}, [%4];" \
                 : "=r"(r0), "=r"(r1), "=r"(r2), "=r"(r3) : "r"(addr))
#define LDSM_X2(r0, r1, addr) \
    asm volatile("ldmatrix.sync.aligned.m8n8.x2.shared.b16 {%0,%1}, [%2];" \
                 : "=r"(r0), "=r"(r1) : "r"(addr))

#define MMA_BF16(c, a0, a1, a2, a3, b0, b1) \
    asm volatile("mma.sync.aligned.m16n8k16.row.col.f32.bf16.bf16.f32 " \
                 "{%0,%1,%2,%3}, {%4,%5,%6,%7}, {%8,%9}, {%0,%1,%2,%3};" \
                 : "+f"((c)[0]), "+f"((c)[1]), "+f"((c)[2]), "+f"((c)[3]) \
                 : "r"(a0), "r"(a1), "r"(a2), "r"(a3), "r"(b0), "r"(b1))

// ---------------- utility kernels ----------------
__global__ void init_state_kernel(const float* __restrict__ hidden,
                                  const float* __restrict__ cell) {
    int i = blockIdx.x * blockDim.x + threadIdx.x;
    if (i < 2 * BATCH * HH) { g_h[i] = hidden[i]; g_c[i] = cell[i]; }
}

__global__ void tail_copy_kernel(float* __restrict__ out) {
    int i = blockIdx.x * blockDim.x + threadIdx.x;
    const long long OFF = (long long)BATCH * TT * VV;
    if (i < 2 * BATCH * HH) {
        out[OFF + i] = g_h[i];
        out[OFF + 2 * BATCH * HH + i] = g_c[i];
    }
}

__global__ void embed_kernel(const int* __restrict__ tgt,
                             const float* __restrict__ emb) {
    int blk = blockIdx.x;             // b*TT + t
    int b = blk >> 6, t = blk & 63;
    int idx = tgt[blk];
    const float4* src = reinterpret_cast<const float4*>(emb + (long long)idx * EE);
    float4* dst = reinterpret_cast<float4*>(g_embT + ((long long)t * BATCH + b) * EE);
    float4 v;
    if (idx == 0) { v.x = v.y = v.z = v.w = 0.f; }
    else          { v = src[threadIdx.x]; }
    dst[threadIdx.x] = v;
}

// split fp32 -> bf16 hi + bf16 lo (residual), 4 elems/thread
__global__ void split_bf16_kernel(const float4* __restrict__ in,
                                  uint2* __restrict__ hi, uint2* __restrict__ lo, int n4) {
    for (int i = blockIdx.x * blockDim.x + threadIdx.x; i < n4; i += gridDim.x * blockDim.x) {
        float4 x = in[i];
        __nv_bfloat16 h0 = __float2bfloat16(x.x), h1 = __float2bfloat16(x.y);
        __nv_bfloat16 h2 = __float2bfloat16(x.z), h3 = __float2bfloat16(x.w);
        __nv_bfloat16 l0 = __float2bfloat16(x.x - __bfloat162float(h0));
        __nv_bfloat16 l1 = __float2bfloat16(x.y - __bfloat162float(h1));
        __nv_bfloat16 l2 = __float2bfloat16(x.z - __bfloat162float(h2));
        __nv_bfloat16 l3 = __float2bfloat16(x.w - __bfloat162float(h3));
        uint2 hv, lv;
        hv.x = (uint32_t)__bfloat16_as_ushort(h0) | ((uint32_t)__bfloat16_as_ushort(h1) << 16);
        hv.y = (uint32_t)__bfloat16_as_ushort(h2) | ((uint32_t)__bfloat16_as_ushort(h3) << 16);
        lv.x = (uint32_t)__bfloat16_as_ushort(l0) | ((uint32_t)__bfloat16_as_ushort(l1) << 16);
        lv.y = (uint32_t)__bfloat16_as_ushort(l2) | ((uint32_t)__bfloat16_as_ushort(l3) << 16);
        hi[i] = hv; lo[i] = lv;
    }
}

// ---------------- small-M (M=32) partial GEMM: C = A @ W^T ----------------
__global__ __launch_bounds__(256)
void gates_kernel(const float* __restrict__ A0, int sA0, const float* __restrict__ W0, int sW0,
                  const float* __restrict__ A1, int sA1, const float* __restrict__ W1, int sW1,
                  const float* __restrict__ A2, int sA2, const float* __restrict__ W2, int sW2,
                  float* __restrict__ Cpart, int ldc) {
    __shared__ float As[32][33];
    __shared__ float Ws[32][68];
    const int tid = threadIdx.x;
    const int jg = tid & 15;
    const int bg = tid >> 4;
    const int j0 = blockIdx.x * 64;
    const int jj0 = jg * 4;
    const int b0 = bg * 2;

    const int op = blockIdx.y >> 2;
    const int ksl = blockIdx.y & 3;

    const float* A = (op == 0) ? A0 : (op == 1) ? A1 : A2;
    const float* W = (op == 0) ? W0 : (op == 1) ? W1 : W2;
    const int sA = (op == 0) ? sA0 : (op == 1) ? sA1 : sA2;
    const int sW = (op == 0) ? sW0 : (op == 1) ? sW1 : sW2;

    float acc[2][4];
    #pragma unroll
    for (int i = 0; i < 2; i++)
        #pragma unroll
        for (int j = 0; j < 4; j++) acc[i][j] = 0.f;

    const int kbase = ksl * 128;
    for (int k0 = kbase; k0 < kbase + 128; k0 += 32) {
        #pragma unroll
        for (int i = 0; i < 4; i++) {
            int e = tid + i * 256;
            int bb = e >> 5, kk = e & 31;
            As[kk][bb] = A[bb * sA + k0 + kk];
        }
        #pragma unroll
        for (int i = 0; i < 8; i++) {
            int e = tid + i * 256;
            int jj = e >> 5, kk = e & 31;
            Ws[kk][jj] = W[(long long)(j0 + jj) * sW + k0 + kk];
        }
        __syncthreads();
        #pragma unroll
        for (int kk = 0; kk < 32; kk++) {
            float a0 = As[kk][b0];
            float a1 = As[kk][b0 + 1];
            float4 wv = *reinterpret_cast<const float4*>(&Ws[kk][jj0]);
            acc[0][0] += a0 * wv.x; acc[0][1] += a0 * wv.y;
            acc[0][2] += a0 * wv.z; acc[0][3] += a0 * wv.w;
            acc[1][0] += a1 * wv.x; acc[1][1] += a1 * wv.y;
            acc[1][2] += a1 * wv.z; acc[1][3] += a1 * wv.w;
        }
        __syncthreads();
    }

    float* C = Cpart + (long long)blockIdx.y * 32 * ldc;
    #pragma unroll
    for (int i = 0; i < 2; i++) {
        int b = b0 + i;
        #pragma unroll
        for (int j = 0; j < 4; j++)
            C[b * ldc + j0 + jj0 + j] = acc[i][j];
    }
}

// ---------------- LSTM elementwise update ----------------
__device__ __forceinline__ float sigmf(float x) { return 1.f / (1.f + expf(-x)); }

__global__ void lstm_update_kernel(const float* __restrict__ gpart, int nslices,
                                   const float* __restrict__ b_ih,
                                   const float* __restrict__ b_hh,
                                   float* __restrict__ h, float* __restrict__ c,
                                   float* __restrict__ feat_h1) {
    int idx = blockIdx.x * blockDim.x + threadIdx.x;
    if (idx >= BATCH * HH) return;
    int b = idx >> 9, u = idx & 511;
    float gi = 0, gf = 0, gg = 0, go = 0;
    for (int s = 0; s < nslices; s++) {
        const float* gp = gpart + (long long)s * BATCH * 2048 + b * 2048;
        gi += gp[u]; gf += gp[512 + u]; gg += gp[1024 + u]; go += gp[1536 + u];
    }
    gi += b_ih[u]        + b_hh[u];
    gf += b_ih[512 + u]  + b_hh[512 + u];
    gg += b_ih[1024 + u] + b_hh[1024 + u];
    go += b_ih[1536 + u] + b_hh[1536 + u];
    float cn = sigmf(gf) * c[idx] + sigmf(gi) * tanhf(gg);
    float hn = sigmf(go) * tanhf(cn);
    c[idx] = cn;
    h[idx] = hn;
    if (feat_h1) feat_h1[b * 1024 + u] = hn;
}

// ---------------- attention ----------------
__global__ void attn_kernel(const float* __restrict__ enc,
                            float* __restrict__ ctx_out) {
    __shared__ float q_sm[HH];
    __shared__ float sc[SS];
    __shared__ float s_red[2];
    const int b = blockIdx.x;
    const int tid = threadIdx.x;
    const int lane = tid & 31;
    const int warp = tid >> 5;

    #pragma unroll
    for (int r = 0; r < 2; r++) {
        int k = tid + r * 256;
        float v = 0.f;
        #pragma unroll
        for (int s = 0; s < 4; s++) v += g_qpart[s * BATCH * HH + b * HH + k];
        q_sm[k] = v;
    }
    __syncthreads();

    const float* encb = enc + (long long)b * SS * HH;
    #pragma unroll
    for (int si = 0; si < 8; si++) {
        int s = warp * 8 + si;
        const float* row = encb + s * HH;
        float sum = 0.f;
        for (int j = lane; j < HH; j += 32) sum += row[j] * q_sm[j];
        #pragma unroll
        for (int o = 16; o; o >>= 1) sum += __shfl_down_sync(0xffffffffu, sum, o);
        if (lane == 0) sc[s] = sum;
    }
    __syncthreads();

    if (tid == 0) {
        float mx = sc[0];
        for (int s = 1; s < SS; s++) mx = fmaxf(mx, sc[s]);
        s_red[0] = mx;
    }
    __syncthreads();
    if (tid < SS) sc[tid] = expf(sc[tid] - s_red[0]);
    __syncthreads();
    if (tid == 0) {
        float sm = 0.f;
        for (int s = 0; s < SS; s++) sm += sc[s];
        s_red[1] = 1.f / sm;
    }
    __syncthreads();
    const float inv = s_red[1];

    for (int k = tid; k < HH; k += 256) {
        float acc = 0.f;
        #pragma unroll 8
        for (int s = 0; s < SS; s++) acc += sc[s] * encb[s * HH + k];
        ctx_out[b * 1024 + k] = acc * inv;
    }
}

// ---------------- tensor-core projection GEMM (mma.sync, 3x bf16 split) -----
// C[2048 x 32000] = feat @ W^T (+bias), with (t,b)->(b,t) output row remap.
// CTA tile 128(m) x 128(n), k-chunks of 32, double-buffered cp.async.
// 8 warps in 4(m) x 2(n) grid; warp tile 32 x 64.
#define GK 1024
#define KC 32
#define NKC (GK / KC)
#define RST 40                       // smem row stride in bf16 (80 B)
#define BUF_BF16 (128 * RST)         // 5120 bf16 per operand buffer
#define STAGE_BF16 (4 * BUF_BF16)    // aH | aL | bH | bL
#define GEMM_SMEM (2 * STAGE_BF16 * 2)  // bytes

__global__ __launch_bounds__(256, 1)
void big_gemm_mma(const __nv_bfloat16* __restrict__ AH, const __nv_bfloat16* __restrict__ AL,
                  const __nv_bfloat16* __restrict__ BH, const __nv_bfloat16* __restrict__ BL,
                  const float* __restrict__ bias, float* __restrict__ out) {
    extern __shared__ __nv_bfloat16 sm[];
    const int tid = threadIdx.x;
    const int lane = tid & 31;
    const int wid = tid >> 5;
    const int wm = wid >> 1;          // 0..3
    const int wn = wid & 1;           // 0..1
    const int m0 = blockIdx.x * 128;
    const int n0 = blockIdx.y * 128;
    const uint32_t smem_base = smem_to_u32(sm);

    float acc[2][8][4];
    #pragma unroll
    for (int i = 0; i < 2; i++)
        #pragma unroll
        for (int j = 0; j < 8; j++)
            #pragma unroll
            for (int v = 0; v < 4; v++) acc[i][j][v] = 0.f;

    // issue cp.async for chunk kc into stage st
    auto load_stage = [&](int st, int kc) {
        const uint32_t sb = smem_base + st * STAGE_BF16 * 2;
        const int k0 = kc * KC;
        #pragma unroll
        for (int r = 0; r < 2; r++) {
            int idx = tid + r * 256;                  // 0..511
            int row = idx >> 2, c = idx & 3;
            uint32_t doff = (uint32_t)(row * RST + c * 8) * 2;
            long long aoff = (long long)(m0 + row) * GK + k0 + c * 8;
            long long boff = (long long)(n0 + row) * GK + k0 + c * 8;
            CP16(sb + doff,                    AH + aoff);
            CP16(sb + BUF_BF16 * 2 + doff,     AL + aoff);
            CP16(sb + BUF_BF16 * 4 + doff,     BH + boff);
            CP16(sb + BUF_BF16 * 6 + doff,     BL + boff);
        }
        CP_COMMIT();
    };

    load_stage(0, 0);

    for (int kc = 0; kc < NKC; kc++) {
        const int st = kc & 1;
        if (kc + 1 < NKC) { load_stage(st ^ 1, kc + 1); CP_WAIT1(); }
        else              { CP_WAIT0(); }
        __syncthreads();

        const uint32_t sb = smem_base + st * STAGE_BF16 * 2;
        // A fragments (hi & lo): [i(m16)][kk(k16)][4]
        uint32_t ah[2][2][4], al[2][2][4];
        #pragma unroll
        for (int i = 0; i < 2; i++)
            #pragma unroll
            for (int kk = 0; kk < 2; kk++) {
                uint32_t addr = sb + (uint32_t)((wm * 32 + i * 16 + (lane & 15)) * RST
                                                + kk * 16 + (lane >> 4) * 8) * 2;
                LDSM_X4(ah[i][kk][0], ah[i][kk][1], ah[i][kk][2], ah[i][kk][3], addr);
                LDSM_X4(al[i][kk][0], al[i][kk][1], al[i][kk][2], al[i][kk][3],
                        addr + BUF_BF16 * 2);
            }
        #pragma unroll
        for (int j = 0; j < 8; j++) {
            #pragma unroll
            for (int kk = 0; kk < 2; kk++) {
                uint32_t baddr = sb + BUF_BF16 * 4
                    + (uint32_t)((wn * 64 + j * 8 + (lane & 7)) * RST
                                 + kk * 16 + ((lane >> 3) & 1) * 8) * 2;
                uint32_t bh0, bh1, bl0, bl1;
                LDSM_X2(bh0, bh1, baddr);
                LDSM_X2(bl0, bl1, baddr + BUF_BF16 * 2);
                #pragma unroll
                for (int i = 0; i < 2; i++) {
                    MMA_BF16(acc[i][j], ah[i][kk][0], ah[i][kk][1], ah[i][kk][2], ah[i][kk][3], bh0, bh1);
                    MMA_BF16(acc[i][j], al[i][kk][0], al[i][kk][1], al[i][kk][2], al[i][kk][3], bh0, bh1);
                    MMA_BF16(acc[i][j], ah[i][kk][0], ah[i][kk][1], ah[i][kk][2], ah[i][kk][3], bl0, bl1);
                }
            }
        }
        __syncthreads();
    }

    // epilogue: direct STG (float2), rows remapped (t,b)->(b,t)
    #pragma unroll
    for (int i = 0; i < 2; i++) {
        int mA = m0 + wm * 32 + i * 16 + (lane >> 2);
        int mB = mA + 8;
        int tA = mA >> 5, bA = mA & 31;
        int tB = mB >> 5, bB = mB & 31;
        float* rowA = out + (long long)((bA << 6) + tA) * VV;
        float* rowB = out + (long long)((bB << 6) + tB) * VV;
        #pragma unroll
        for (int j = 0; j < 8; j++) {
            int n = n0 + wn * 64 + j * 8 + (lane & 3) * 2;
            float bv0 = bias[n], bv1 = bias[n + 1];
            float2 vA = make_float2(acc[i][j][0] + bv0, acc[i][j][1] + bv1);
            float2 vB = make_float2(acc[i][j][2] + bv0, acc[i][j][3] + bv1);
            *reinterpret_cast<float2*>(rowA + n) = vA;
            *reinterpret_cast<float2*>(rowB + n) = vB;
        }
    }
}

// ---------------- host launcher ----------------
extern "C" void kernel_launch(void* const* d_in, const int* in_sizes, int n_in,
                              void* d_out, int out_size) {
    const int*   tgt    = (const int*)  d_in[0];
    const float* enc    = (const float*)d_in[1];
    const float* hidden = (const float*)d_in[2];
    const float* cell   = (const float*)d_in[3];
    const float* emb    = (const float*)d_in[4];
    const float* W_a    = (const float*)d_in[5];
    const float* W_ih0  = (const float*)d_in[6];
    const float* W_hh0  = (const float*)d_in[7];
    const float* b_ih0  = (const float*)d_in[8];
    const float* b_hh0  = (const float*)d_in[9];
    const float* W_ih1  = (const float*)d_in[10];
    const float* W_hh1  = (const float*)d_in[11];
    const float* b_ih1  = (const float*)d_in[12];
    const float* b_hh1  = (const float*)d_in[13];
    const float* W_out  = (const float*)d_in[14];
    const float* b_out  = (const float*)d_in[15];
    float* out = (float*)d_out;

    float *p_embT, *p_h, *p_c, *p_feat, *p_gpart, *p_qpart;
    __nv_bfloat16 *p_WH, *p_WL, *p_fH, *p_fL;
    cudaGetSymbolAddress((void**)&p_embT,  g_embT);
    cudaGetSymbolAddress((void**)&p_h,     g_h);
    cudaGetSymbolAddress((void**)&p_c,     g_c);
    cudaGetSymbolAddress((void**)&p_feat,  g_feat);
    cudaGetSymbolAddress((void**)&p_gpart, g_gpart);
    cudaGetSymbolAddress((void**)&p_qpart, g_qpart);
    cudaGetSymbolAddress((void**)&p_WH,    g_WH);
    cudaGetSymbolAddress((void**)&p_WL,    g_WL);
    cudaGetSymbolAddress((void**)&p_fH,    g_fH);
    cudaGetSymbolAddress((void**)&p_fL,    g_fL);

    init_state_kernel<<<64, 512>>>(hidden, cell);
    embed_kernel<<<BATCH * TT, 128>>>(tgt, emb);
    // split W_out into bf16 hi/lo (independent of recurrence)
    split_bf16_kernel<<<4096, 256>>>((const float4*)W_out, (uint2*)p_WH, (uint2*)p_WL,
                                     VV * 1024 / 4);

    for (int t = 0; t < TT; t++) {
        float* embT_t = p_embT + (long long)t * BATCH * EE;
        float* feat_t = p_feat + (long long)t * BATCH * 1024;
        float* ctx_t  = feat_t + 512;

        // q[b,j] = sum_k W_a[j,k] * h1[b,k]
        gates_kernel<<<dim3(8, 4), 256>>>(
            p_h + BATCH * HH, 512, W_a, 512,
            p_h, 512, W_a, 512,
            p_h, 512, W_a, 512,
            p_qpart, 512);

        attn_kernel<<<32, 256>>>(enc, ctx_t);

        gates_kernel<<<dim3(32, 12), 256>>>(
            embT_t, 512, W_ih0, 1024,
            ctx_t, 1024, W_ih0 + 512, 1024,
            p_h, 512, W_hh0, 512,
            p_gpart, 2048);
        lstm_update_kernel<<<64, 256>>>(p_gpart, 12, b_ih0, b_hh0,
                                        p_h, p_c, nullptr);

        gates_kernel<<<dim3(32, 8), 256>>>(
            p_h, 512, W_ih1, 512,
            p_h + BATCH * HH, 512, W_hh1, 512,
            p_h, 512, W_ih1, 512,
            p_gpart, 2048);
        lstm_update_kernel<<<64, 256>>>(p_gpart, 8, b_ih1, b_hh1,
                                        p_h + BATCH * HH, p_c + BATCH * HH,
                                        feat_t);
    }

    // split feat into bf16 hi/lo
    split_bf16_kernel<<<2048, 256>>>((const float4*)p_feat, (uint2*)p_fH, (uint2*)p_fL,
                                     2048 * 1024 / 4);

    // tensor-core projection via mma.sync
    cudaFuncSetAttribute(big_gemm_mma, cudaFuncAttributeMaxDynamicSharedMemorySize, GEMM_SMEM);
    big_gemm_mma<<<dim3(16, VV / 128), 256, GEMM_SMEM>>>(p_fH, p_fL, p_WH, p_WL, b_out, out);

    tail_copy_kernel<<<64, 512>>>(out);
}